// round 2
// baseline (speedup 1.0000x reference)
#include <cuda_runtime.h>
#include <math.h>

#define BB  8
#define LL  512
#define KK  16
#define EE  32
#define NHH 64
#define GG  192

// -------- scratch (static device globals; no runtime allocation) --------
__device__ float g_q[BB*LL*EE];
__device__ float g_k[BB*LL*EE];
__device__ float g_S[BB*LL*LL];      // scores / sqrt(32)
__device__ int   g_bcnt[BB*KK];
__device__ int   g_bidx[BB*KK*LL];   // per (b,c) ordered list of positions
__device__ float g_M2[GG*KK];        // W_ih @ Wo   (192 x 16)
__device__ float g_cc[GG];           // W_ih @ bo + b_ih
__device__ float g_GI[BB*LL*GG];     // precomputed input gates

// -------- kernel 1: key_emb + Q/K projection --------
__global__ void k_prep(const float* __restrict__ ts,
                       const float* __restrict__ Wl, const float* __restrict__ bl,
                       const float* __restrict__ Wp, const float* __restrict__ bp,
                       const float* __restrict__ Wq, const float* __restrict__ bq,
                       const float* __restrict__ Wk, const float* __restrict__ bk) {
    __shared__ float sWq[EE*EE], sWk[EE*EE], sWp[EE], sbp[EE], sbq[EE], sbk[EE];
    __shared__ float sWl, sbl;
    int tid = threadIdx.x;
    for (int i = tid; i < EE*EE; i += blockDim.x) { sWq[i] = Wq[i]; sWk[i] = Wk[i]; }
    if (tid < EE-1) { sWp[tid] = Wp[tid]; sbp[tid] = bp[tid]; }
    if (tid < EE)   { sbq[tid] = bq[tid]; sbk[tid] = bk[tid]; }
    if (tid == 0)   { sWl = Wl[0]; sbl = bl[0]; }
    __syncthreads();
    int idx = blockIdx.x * blockDim.x + tid;      // (b*L + l)
    float t = ts[idx];
    float ke[EE];
    ke[0] = t * sWl + sbl;
    #pragma unroll
    for (int i = 1; i < EE; i++) ke[i] = sinf(t * sWp[i-1] + sbp[i-1]);
    #pragma unroll 4
    for (int e = 0; e < EE; e++) {
        float aq = sbq[e], ak = sbk[e];
        #pragma unroll
        for (int j = 0; j < EE; j++) {
            aq += sWq[e*EE+j] * ke[j];
            ak += sWk[e*EE+j] * ke[j];
        }
        g_q[idx*EE+e] = aq;
        g_k[idx*EE+e] = ak;
    }
}

// -------- kernel 2: per-(b,category) ordered position buckets --------
__global__ void k_bucket(const int* __restrict__ mark, const float* __restrict__ npm) {
    int b = blockIdx.x, c = threadIdx.x;   // 16 threads/block
    int pos = 0;
    for (int k = 0; k < LL; k++) {
        int   mk = mark[b*LL+k];
        float np = npm[b*LL+k];            // non_pad_mask[b,k,0]
        if (mk == c+1 && np > 0.f) { g_bidx[(b*KK+c)*LL + pos] = k; pos++; }
    }
    g_bcnt[b*KK+c] = pos;
}

// -------- kernel 3: fold Wo into W_ih:  M2 = W_ih@Wo, cc = W_ih@bo + b_ih --------
__global__ void k_m2(const float* __restrict__ W_ih, const float* __restrict__ Wo,
                     const float* __restrict__ b_ih, const float* __restrict__ bo) {
    int g = threadIdx.x;  // 192 threads
    float wrow[NHH];
    #pragma unroll
    for (int o = 0; o < NHH; o++) wrow[o] = W_ih[g*NHH+o];
    float cc = b_ih[g];
    #pragma unroll
    for (int o = 0; o < NHH; o++) cc += wrow[o] * bo[o];
    g_cc[g] = cc;
    for (int c = 0; c < KK; c++) {
        float a = 0.f;
        #pragma unroll
        for (int o = 0; o < NHH; o++) a += wrow[o] * Wo[o*KK+c];
        g_M2[g*KK+c] = a;
    }
}

// -------- kernel 4: scores = q @ k^T / sqrt(32)  (tiled, smem) --------
__global__ void k_scores() {
    __shared__ float q_s[32*33];
    __shared__ float k_s[64*33];
    int tid = threadIdx.x;                 // 256 threads
    int b = blockIdx.y;
    int qbase = blockIdx.x * 32;
    for (int i = tid; i < 32*EE; i += 256) {
        int r = i >> 5, e = i & 31;
        q_s[r*33+e] = g_q[(b*LL + qbase + r)*EE + e];
    }
    int ql = tid >> 3, kg = tid & 7;
    const float sc = 0.17677669529663687f; // 1/sqrt(32)
    for (int kt = 0; kt < 8; kt++) {
        __syncthreads();
        for (int i = tid; i < 64*EE; i += 256) {
            int r = i >> 5, e = i & 31;
            k_s[r*33+e] = g_k[(b*LL + kt*64 + r)*EE + e];
        }
        __syncthreads();
        float acc[8];
        #pragma unroll
        for (int i = 0; i < 8; i++) acc[i] = 0.f;
        #pragma unroll
        for (int e = 0; e < EE; e++) {
            float qv = q_s[ql*33+e];
            #pragma unroll
            for (int i = 0; i < 8; i++) acc[i] += qv * k_s[(kg*8+i)*33+e];
        }
        float* so = &g_S[((size_t)(b*LL) + qbase + ql)*LL + kt*64 + kg*8];
        #pragma unroll
        for (int i = 0; i < 8; i++) so[i] = acc[i] * sc;
    }
}

// -------- kernel 5: bucketed softmax + fused (Wo,W_ih) epilogue -> GI --------
__global__ void k_att(const float* __restrict__ val) {
    __shared__ float val_s[LL];
    __shared__ int   cnt_s[KK];
    __shared__ float x_s[32*KK];
    __shared__ float M2_s[GG*17];          // padded stride 17 (conflict-free)
    __shared__ float cc_s[GG];
    int tid = threadIdx.x;                 // 512 threads = 16 warps
    int b = blockIdx.y;
    int qbase = blockIdx.x * 32;
    for (int i = tid; i < LL; i += 512) val_s[i] = val[b*LL+i];
    if (tid < KK) cnt_s[tid] = g_bcnt[b*KK+tid];
    for (int i = tid; i < GG*KK; i += 512) {
        int g = i >> 4, c = i & 15;
        M2_s[g*17+c] = g_M2[i];
    }
    if (tid < GG) cc_s[tid] = g_cc[tid];
    __syncthreads();

    int wid = tid >> 5, lane = tid & 31;
    for (int task = wid; task < 32*KK; task += 16) {
        int ql = task >> 4, c = task & 15;
        int q = qbase + ql;
        int cnt = cnt_s[c];
        // online softmax over this category's bucket.
        // logit = s if k <= q+1 else 0 (W_OFF=1): future-masked positions with
        // matching mark still contribute exp(0) — matches reference exactly.
        float m = -1e30f, se = 0.f, sv = 0.f;
        for (int i = lane; i < cnt; i += 32) {
            int   kk = g_bidx[(b*KK+c)*LL + i];
            float s  = g_S[((size_t)(b*LL) + q)*LL + kk];
            float lg = (kk <= q+1) ? s : 0.f;
            float v  = val_s[kk];
            float nm = fmaxf(m, lg);
            float ea = __expf(m - nm), eb = __expf(lg - nm);
            se = se*ea + eb;
            sv = sv*ea + eb*v;
            m = nm;
        }
        #pragma unroll
        for (int off = 16; off > 0; off >>= 1) {
            float mo  = __shfl_xor_sync(0xffffffffu, m,  off);
            float seo = __shfl_xor_sync(0xffffffffu, se, off);
            float svo = __shfl_xor_sync(0xffffffffu, sv, off);
            float nm = fmaxf(m, mo);
            float ea = __expf(m - nm), eb = __expf(mo - nm);
            se = se*ea + seo*eb;
            sv = sv*ea + svo*eb;
            m = nm;
        }
        if (lane == 0) x_s[ql*KK+c] = (se > 0.f) ? sv/se : 0.f;
    }
    __syncthreads();

    // GI[b, q, g] = cc[g] + sum_c M2[g][c] * x[q][c]
    for (int o = tid; o < 32*GG; o += 512) {
        int ql = o / GG, g = o % GG;
        float acc = cc_s[g];
        #pragma unroll
        for (int c = 0; c < KK; c++) acc += M2_s[g*17+c] * x_s[ql*KK+c];
        g_GI[((size_t)(b*LL) + qbase + ql)*GG + g] = acc;
    }
}

// -------- kernel 6: GRU scan — one block per independent batch chain --------
__global__ void __launch_bounds__(GG) k_gru(const float* __restrict__ W_hh,
                                            const float* __restrict__ b_hh,
                                            float* __restrict__ out) {
    int b = blockIdx.x, t = threadIdx.x;   // 192 threads: one per gate row
    __shared__ __align__(16) float h_s[NHH];
    __shared__ float gh_s[GG];
    float w[NHH];
    #pragma unroll
    for (int j = 0; j < NHH; j++) w[j] = W_hh[t*NHH + j];
    float bh = b_hh[t];
    if (t < NHH) h_s[t] = 0.f;

    float g0 = 0.f, g1 = 0.f, g2 = 0.f;    // current-step input gates
    if (t < NHH) {
        const float* gp = g_GI + (size_t)b*LL*GG;
        g0 = gp[t]; g1 = gp[t+NHH]; g2 = gp[t+2*NHH];
    }
    __syncthreads();

    for (int l = 0; l < LL; l++) {
        // prefetch next step's input gates early (L2 latency hides under matvec)
        float n0 = 0.f, n1 = 0.f, n2 = 0.f;
        if (t < NHH && l+1 < LL) {
            const float* gp = g_GI + ((size_t)b*LL + l + 1)*GG;
            n0 = gp[t]; n1 = gp[t+NHH]; n2 = gp[t+2*NHH];
        }
        // gh[t] = W_hh[t,:] . h  (weights in registers, 4 accumulator chains)
        float a0 = bh, a1 = 0.f, a2 = 0.f, a3 = 0.f;
        const float4* h4 = (const float4*)h_s;
        #pragma unroll
        for (int j4 = 0; j4 < NHH/4; j4++) {
            float4 hv = h4[j4];
            a0 += w[4*j4+0]*hv.x;
            a1 += w[4*j4+1]*hv.y;
            a2 += w[4*j4+2]*hv.z;
            a3 += w[4*j4+3]*hv.w;
        }
        gh_s[t] = (a0+a1) + (a2+a3);
        __syncthreads();
        if (t < NHH) {
            float hr = gh_s[t], hz = gh_s[t+NHH], hn = gh_s[t+2*NHH];
            float r = 1.f/(1.f + __expf(-(g0 + hr)));
            float z = 1.f/(1.f + __expf(-(g1 + hz)));
            float pre = g2 + r*hn;
            float cp = fminf(fmaxf(pre, -15.f), 15.f);
            float e2 = __expf(2.f*cp);
            float n  = (e2 - 1.f)/(e2 + 1.f);      // tanh
            float hnew = (1.f - z)*n + z*h_s[t];
            out[((size_t)b*LL + l)*NHH + t] = hnew;
            h_s[t] = hnew;
            g0 = n0; g1 = n1; g2 = n2;
        }
        __syncthreads();
    }
}

// -------- launch --------
extern "C" void kernel_launch(void* const* d_in, const int* in_sizes, int n_in,
                              void* d_out, int out_size) {
    const float* ts   = (const float*)d_in[0];
    const float* val  = (const float*)d_in[1];
    const int*   mark = (const int*)  d_in[2];
    const float* npm  = (const float*)d_in[3];
    const float* Wl   = (const float*)d_in[4];
    const float* bl   = (const float*)d_in[5];
    const float* Wp   = (const float*)d_in[6];
    const float* bp   = (const float*)d_in[7];
    const float* Wq   = (const float*)d_in[8];
    const float* bq   = (const float*)d_in[9];
    const float* Wk   = (const float*)d_in[10];
    const float* bk   = (const float*)d_in[11];
    const float* Wo   = (const float*)d_in[12];
    const float* bo   = (const float*)d_in[13];
    const float* W_ih = (const float*)d_in[14];
    const float* W_hh = (const float*)d_in[15];
    const float* b_ih = (const float*)d_in[16];
    const float* b_hh = (const float*)d_in[17];
    float* out = (float*)d_out;

    k_prep  <<<32, 128>>>(ts, Wl, bl, Wp, bp, Wq, bq, Wk, bk);
    k_bucket<<<8, 16>>>(mark, npm);
    k_m2    <<<1, 192>>>(W_ih, Wo, b_ih, bo);
    k_scores<<<dim3(16,8), 256>>>();
    k_att   <<<dim3(16,8), 512>>>(val);
    k_gru   <<<8, 192>>>(W_hh, b_hh, out);
}

// round 3
// speedup vs baseline: 1.0004x; 1.0004x over previous
#include <cuda_runtime.h>
#include <math.h>

#define BB  8
#define LL  512
#define KK  16
#define EE  32
#define NHH 64
#define GG  192

// -------- scratch (static device globals; no runtime allocation) --------
__device__ float g_q[BB*LL*EE];
__device__ float g_k[BB*LL*EE];
__device__ float g_S[BB*LL*LL];      // scores / sqrt(32)
__device__ int   g_bcnt[BB*KK];
__device__ int   g_bidx[BB*KK*LL];   // per (b,c) ordered list of positions
__device__ float g_M2[GG*KK];        // W_ih @ Wo   (192 x 16)
__device__ float g_cc[GG];           // W_ih @ bo + b_ih
__device__ float g_GI[BB*LL*GG];     // precomputed input gates

// -------- kernel 1: key_emb + Q/K projection --------
__global__ void k_prep(const float* __restrict__ ts,
                       const float* __restrict__ Wl, const float* __restrict__ bl,
                       const float* __restrict__ Wp, const float* __restrict__ bp,
                       const float* __restrict__ Wq, const float* __restrict__ bq,
                       const float* __restrict__ Wk, const float* __restrict__ bk) {
    __shared__ float sWq[EE*EE], sWk[EE*EE], sWp[EE], sbp[EE], sbq[EE], sbk[EE];
    __shared__ float sWl, sbl;
    int tid = threadIdx.x;
    for (int i = tid; i < EE*EE; i += blockDim.x) { sWq[i] = Wq[i]; sWk[i] = Wk[i]; }
    if (tid < EE-1) { sWp[tid] = Wp[tid]; sbp[tid] = bp[tid]; }
    if (tid < EE)   { sbq[tid] = bq[tid]; sbk[tid] = bk[tid]; }
    if (tid == 0)   { sWl = Wl[0]; sbl = bl[0]; }
    __syncthreads();
    int idx = blockIdx.x * blockDim.x + tid;      // (b*L + l)
    float t = ts[idx];
    float ke[EE];
    ke[0] = t * sWl + sbl;
    #pragma unroll
    for (int i = 1; i < EE; i++) ke[i] = sinf(t * sWp[i-1] + sbp[i-1]);
    #pragma unroll 4
    for (int e = 0; e < EE; e++) {
        float aq = sbq[e], ak = sbk[e];
        #pragma unroll
        for (int j = 0; j < EE; j++) {
            aq += sWq[e*EE+j] * ke[j];
            ak += sWk[e*EE+j] * ke[j];
        }
        g_q[idx*EE+e] = aq;
        g_k[idx*EE+e] = ak;
    }
}

// -------- kernel 2: per-(b,category) ordered position buckets --------
__global__ void k_bucket(const int* __restrict__ mark, const float* __restrict__ npm) {
    int b = blockIdx.x, c = threadIdx.x;   // 16 threads/block
    int pos = 0;
    for (int k = 0; k < LL; k++) {
        int   mk = mark[b*LL+k];
        float np = npm[b*LL+k];            // non_pad_mask[b,k,0]
        if (mk == c+1 && np > 0.f) { g_bidx[(b*KK+c)*LL + pos] = k; pos++; }
    }
    g_bcnt[b*KK+c] = pos;
}

// -------- kernel 3: fold Wo into W_ih:  M2 = W_ih@Wo, cc = W_ih@bo + b_ih --------
__global__ void k_m2(const float* __restrict__ W_ih, const float* __restrict__ Wo,
                     const float* __restrict__ b_ih, const float* __restrict__ bo) {
    int g = threadIdx.x;  // 192 threads
    float wrow[NHH];
    #pragma unroll
    for (int o = 0; o < NHH; o++) wrow[o] = W_ih[g*NHH+o];
    float cc = b_ih[g];
    #pragma unroll
    for (int o = 0; o < NHH; o++) cc += wrow[o] * bo[o];
    g_cc[g] = cc;
    for (int c = 0; c < KK; c++) {
        float a = 0.f;
        #pragma unroll
        for (int o = 0; o < NHH; o++) a += wrow[o] * Wo[o*KK+c];
        g_M2[g*KK+c] = a;
    }
}

// -------- kernel 4: scores = q @ k^T / sqrt(32)  (tiled, smem) --------
__global__ void k_scores() {
    __shared__ float q_s[32*33];
    __shared__ float k_s[64*33];
    int tid = threadIdx.x;                 // 256 threads
    int b = blockIdx.y;
    int qbase = blockIdx.x * 32;
    for (int i = tid; i < 32*EE; i += 256) {
        int r = i >> 5, e = i & 31;
        q_s[r*33+e] = g_q[(b*LL + qbase + r)*EE + e];
    }
    int ql = tid >> 3, kg = tid & 7;
    const float sc = 0.17677669529663687f; // 1/sqrt(32)
    for (int kt = 0; kt < 8; kt++) {
        __syncthreads();
        for (int i = tid; i < 64*EE; i += 256) {
            int r = i >> 5, e = i & 31;
            k_s[r*33+e] = g_k[(b*LL + kt*64 + r)*EE + e];
        }
        __syncthreads();
        float acc[8];
        #pragma unroll
        for (int i = 0; i < 8; i++) acc[i] = 0.f;
        #pragma unroll
        for (int e = 0; e < EE; e++) {
            float qv = q_s[ql*33+e];
            #pragma unroll
            for (int i = 0; i < 8; i++) acc[i] += qv * k_s[(kg*8+i)*33+e];
        }
        float* so = &g_S[((size_t)(b*LL) + qbase + ql)*LL + kt*64 + kg*8];
        #pragma unroll
        for (int i = 0; i < 8; i++) so[i] = acc[i] * sc;
    }
}

// -------- kernel 5: bucketed softmax + fused (Wo,W_ih) epilogue -> GI --------
__global__ void k_att(const float* __restrict__ val) {
    __shared__ float val_s[LL];
    __shared__ int   cnt_s[KK];
    __shared__ float x_s[32*KK];
    __shared__ float M2_s[GG*17];          // padded stride 17 (conflict-free)
    __shared__ float cc_s[GG];
    int tid = threadIdx.x;                 // 512 threads = 16 warps
    int b = blockIdx.y;
    int qbase = blockIdx.x * 32;
    for (int i = tid; i < LL; i += 512) val_s[i] = val[b*LL+i];
    if (tid < KK) cnt_s[tid] = g_bcnt[b*KK+tid];
    for (int i = tid; i < GG*KK; i += 512) {
        int g = i >> 4, c = i & 15;
        M2_s[g*17+c] = g_M2[i];
    }
    if (tid < GG) cc_s[tid] = g_cc[tid];
    __syncthreads();

    int wid = tid >> 5, lane = tid & 31;
    for (int task = wid; task < 32*KK; task += 16) {
        int ql = task >> 4, c = task & 15;
        int q = qbase + ql;
        int cnt = cnt_s[c];
        // online softmax over this category's bucket.
        // logit = s if k <= q+1 else 0 (W_OFF=1): future-masked positions with
        // matching mark still contribute exp(0) — matches reference exactly.
        float m = -1e30f, se = 0.f, sv = 0.f;
        for (int i = lane; i < cnt; i += 32) {
            int   kk = g_bidx[(b*KK+c)*LL + i];
            float s  = g_S[((size_t)(b*LL) + q)*LL + kk];
            float lg = (kk <= q+1) ? s : 0.f;
            float v  = val_s[kk];
            float nm = fmaxf(m, lg);
            float ea = __expf(m - nm), eb = __expf(lg - nm);
            se = se*ea + eb;
            sv = sv*ea + eb*v;
            m = nm;
        }
        #pragma unroll
        for (int off = 16; off > 0; off >>= 1) {
            float mo  = __shfl_xor_sync(0xffffffffu, m,  off);
            float seo = __shfl_xor_sync(0xffffffffu, se, off);
            float svo = __shfl_xor_sync(0xffffffffu, sv, off);
            float nm = fmaxf(m, mo);
            float ea = __expf(m - nm), eb = __expf(mo - nm);
            se = se*ea + seo*eb;
            sv = sv*ea + svo*eb;
            m = nm;
        }
        if (lane == 0) x_s[ql*KK+c] = (se > 0.f) ? sv/se : 0.f;
    }
    __syncthreads();

    // GI[b, q, g] = cc[g] + sum_c M2[g][c] * x[q][c]
    for (int o = tid; o < 32*GG; o += 512) {
        int ql = o / GG, g = o % GG;
        float acc = cc_s[g];
        #pragma unroll
        for (int c = 0; c < KK; c++) acc += M2_s[g*17+c] * x_s[ql*KK+c];
        g_GI[((size_t)(b*LL) + qbase + ql)*GG + g] = acc;
    }
}

// -------- kernel 6: GRU scan — one block per independent batch chain --------
__global__ void __launch_bounds__(GG) k_gru(const float* __restrict__ W_hh,
                                            const float* __restrict__ b_hh,
                                            float* __restrict__ out) {
    int b = blockIdx.x, t = threadIdx.x;   // 192 threads: one per gate row
    __shared__ __align__(16) float h_s[NHH];
    __shared__ float gh_s[GG];
    float w[NHH];
    #pragma unroll
    for (int j = 0; j < NHH; j++) w[j] = W_hh[t*NHH + j];
    float bh = b_hh[t];
    if (t < NHH) h_s[t] = 0.f;

    float g0 = 0.f, g1 = 0.f, g2 = 0.f;    // current-step input gates
    if (t < NHH) {
        const float* gp = g_GI + (size_t)b*LL*GG;
        g0 = gp[t]; g1 = gp[t+NHH]; g2 = gp[t+2*NHH];
    }
    __syncthreads();

    for (int l = 0; l < LL; l++) {
        // prefetch next step's input gates early (L2 latency hides under matvec)
        float n0 = 0.f, n1 = 0.f, n2 = 0.f;
        if (t < NHH && l+1 < LL) {
            const float* gp = g_GI + ((size_t)b*LL + l + 1)*GG;
            n0 = gp[t]; n1 = gp[t+NHH]; n2 = gp[t+2*NHH];
        }
        // gh[t] = W_hh[t,:] . h  (weights in registers, 4 accumulator chains)
        float a0 = bh, a1 = 0.f, a2 = 0.f, a3 = 0.f;
        const float4* h4 = (const float4*)h_s;
        #pragma unroll
        for (int j4 = 0; j4 < NHH/4; j4++) {
            float4 hv = h4[j4];
            a0 += w[4*j4+0]*hv.x;
            a1 += w[4*j4+1]*hv.y;
            a2 += w[4*j4+2]*hv.z;
            a3 += w[4*j4+3]*hv.w;
        }
        gh_s[t] = (a0+a1) + (a2+a3);
        __syncthreads();
        if (t < NHH) {
            float hr = gh_s[t], hz = gh_s[t+NHH], hn = gh_s[t+2*NHH];
            float r = 1.f/(1.f + __expf(-(g0 + hr)));
            float z = 1.f/(1.f + __expf(-(g1 + hz)));
            float pre = g2 + r*hn;
            float cp = fminf(fmaxf(pre, -15.f), 15.f);
            float e2 = __expf(2.f*cp);
            float n  = (e2 - 1.f)/(e2 + 1.f);      // tanh
            float hnew = (1.f - z)*n + z*h_s[t];
            out[((size_t)b*LL + l)*NHH + t] = hnew;
            h_s[t] = hnew;
            g0 = n0; g1 = n1; g2 = n2;
        }
        __syncthreads();
    }
}

// -------- launch --------
extern "C" void kernel_launch(void* const* d_in, const int* in_sizes, int n_in,
                              void* d_out, int out_size) {
    const float* ts   = (const float*)d_in[0];
    const float* val  = (const float*)d_in[1];
    const int*   mark = (const int*)  d_in[2];
    const float* npm  = (const float*)d_in[3];
    const float* Wl   = (const float*)d_in[4];
    const float* bl   = (const float*)d_in[5];
    const float* Wp   = (const float*)d_in[6];
    const float* bp   = (const float*)d_in[7];
    const float* Wq   = (const float*)d_in[8];
    const float* bq   = (const float*)d_in[9];
    const float* Wk   = (const float*)d_in[10];
    const float* bk   = (const float*)d_in[11];
    const float* Wo   = (const float*)d_in[12];
    const float* bo   = (const float*)d_in[13];
    const float* W_ih = (const float*)d_in[14];
    const float* W_hh = (const float*)d_in[15];
    const float* b_ih = (const float*)d_in[16];
    const float* b_hh = (const float*)d_in[17];
    float* out = (float*)d_out;

    k_prep  <<<32, 128>>>(ts, Wl, bl, Wp, bp, Wq, bq, Wk, bk);
    k_bucket<<<8, 16>>>(mark, npm);
    k_m2    <<<1, 192>>>(W_ih, Wo, b_ih, bo);
    k_scores<<<dim3(16,8), 256>>>();
    k_att   <<<dim3(16,8), 512>>>(val);
    k_gru   <<<8, 192>>>(W_hh, b_hh, out);
}

// round 4
// speedup vs baseline: 1.0603x; 1.0598x over previous
#include <cuda_runtime.h>
#include <math.h>

#define BB  8
#define LL  512
#define KK  16
#define EE  32
#define NHH 64
#define GG  192

// -------- scratch (static device globals; no runtime allocation) --------
__device__ float g_q[BB*LL*EE];
__device__ float g_k[BB*LL*EE];
__device__ int   g_bcnt[BB*KK];
__device__ int   g_bidx[BB*KK*LL];   // per (b,c) ordered list of positions
__device__ float g_M2[GG*KK];        // W_ih @ Wo   (192 x 16)
__device__ float g_cc[GG];           // W_ih @ bo + b_ih
__device__ float g_GI[BB*LL*GG];     // precomputed input gates

__device__ __forceinline__ float tanh_fast(float x) {
    float y;
    asm("tanh.approx.f32 %0, %1;" : "=f"(y) : "f"(x));
    return y;
}
#define FMA2(acc, x, y) \
    asm("fma.rn.f32x2 %0, %1, %2, %0;" : "+l"(acc) : "l"(x), "l"(y))

// -------- kernel 1: fused setup (prep / buckets / Wo-fold), 17 blocks --------
__global__ void k_setup(const float* __restrict__ ts,
                        const float* __restrict__ Wl, const float* __restrict__ bl,
                        const float* __restrict__ Wp, const float* __restrict__ bp,
                        const float* __restrict__ Wq, const float* __restrict__ bq,
                        const float* __restrict__ Wk, const float* __restrict__ bk,
                        const int*   __restrict__ mark, const float* __restrict__ npm,
                        const float* __restrict__ W_ih, const float* __restrict__ Wo,
                        const float* __restrict__ b_ih, const float* __restrict__ bo) {
    int blk = blockIdx.x, tid = threadIdx.x;
    if (blk < 8) {
        // ---- key_emb + Q/K projection: one (b,l) row per thread ----
        __shared__ float sWq[EE*EE], sWk[EE*EE], sWp[EE], sbp[EE], sbq[EE], sbk[EE];
        __shared__ float sWl, sbl;
        for (int i = tid; i < EE*EE; i += blockDim.x) { sWq[i] = Wq[i]; sWk[i] = Wk[i]; }
        if (tid < EE-1) { sWp[tid] = Wp[tid]; sbp[tid] = bp[tid]; }
        if (tid < EE)   { sbq[tid] = bq[tid]; sbk[tid] = bk[tid]; }
        if (tid == 0)   { sWl = Wl[0]; sbl = bl[0]; }
        __syncthreads();
        int idx = blk*LL + tid;               // b = blk, l = tid
        float t = ts[idx];
        float ke[EE];
        ke[0] = t * sWl + sbl;
        #pragma unroll
        for (int i = 1; i < EE; i++) ke[i] = sinf(t * sWp[i-1] + sbp[i-1]);
        #pragma unroll 4
        for (int e = 0; e < EE; e++) {
            float aq = sbq[e], ak = sbk[e];
            #pragma unroll
            for (int j = 0; j < EE; j++) {
                aq += sWq[e*EE+j] * ke[j];
                ak += sWk[e*EE+j] * ke[j];
            }
            g_q[idx*EE+e] = aq;
            g_k[idx*EE+e] = ak;
        }
    } else if (blk < 16) {
        // ---- bucket build: warp per category, ballot compaction ----
        int b = blk - 8;
        int c = tid >> 5, lane = tid & 31;    // 16 warps = 16 categories
        int base = 0;
        for (int ch = 0; ch < LL/32; ch++) {
            int k = ch*32 + lane;
            int   mk = mark[b*LL+k];
            float np = npm[b*LL+k];
            bool hit = (mk == c+1) && (np > 0.f);
            unsigned m = __ballot_sync(0xffffffffu, hit);
            if (hit) g_bidx[(b*KK+c)*LL + base + __popc(m & ((1u<<lane)-1u))] = k;
            base += __popc(m);
        }
        if (lane == 0) g_bcnt[b*KK+c] = base;
    } else {
        // ---- fold Wo into W_ih: M2 = W_ih@Wo, cc = W_ih@bo + b_ih ----
        if (tid < GG) {
            int g = tid;
            float wrow[NHH];
            #pragma unroll
            for (int o = 0; o < NHH; o++) wrow[o] = W_ih[g*NHH+o];
            float cc = b_ih[g];
            #pragma unroll
            for (int o = 0; o < NHH; o++) cc += wrow[o] * bo[o];
            g_cc[g] = cc;
            for (int c = 0; c < KK; c++) {
                float a = 0.f;
                #pragma unroll
                for (int o = 0; o < NHH; o++) a += wrow[o] * Wo[o*KK+c];
                g_M2[g*KK+c] = a;
            }
        }
    }
}

// -------- kernel 2: fused scores(GEMM-in-smem) + bucketed softmax + GI --------
// dynamic smem layout (floats):
#define SOFF_S    0            // 32*512  score tile
#define SOFF_KB   16384        // 64*33   k staging
#define SOFF_Q    18496        // 32*33
#define SOFF_VAL  19552        // 512
#define SOFF_X    20064        // 512
#define SOFF_M2   20576        // 192*17
#define SOFF_CC   23840        // 192
#define SOFF_CNT  24032        // 16 ints
#define SMEM_ATT_BYTES (24032*4 + 16*4)

__global__ void k_att2(const float* __restrict__ val) {
    extern __shared__ float sm[];
    float* S_s   = sm + SOFF_S;
    float* kbuf  = sm + SOFF_KB;
    float* q_s   = sm + SOFF_Q;
    float* val_s = sm + SOFF_VAL;
    float* x_s   = sm + SOFF_X;
    float* M2_s  = sm + SOFF_M2;
    float* cc_s  = sm + SOFF_CC;
    int*   cnt_s = (int*)(sm + SOFF_CNT);

    int tid = threadIdx.x;                 // 512 threads = 16 warps
    int b = blockIdx.y;
    int qbase = blockIdx.x * 32;

    for (int i = tid; i < LL; i += 512) val_s[i] = val[b*LL+i];
    if (tid < KK) cnt_s[tid] = g_bcnt[b*KK+tid];
    for (int i = tid; i < GG*KK; i += 512) {
        int g = i >> 4, c = i & 15;
        M2_s[g*17+c] = g_M2[i];
    }
    if (tid < GG) cc_s[tid] = g_cc[tid];
    for (int i = tid; i < 32*EE; i += 512) {
        int r = i >> 5, e = i & 31;
        q_s[r*33+e] = g_q[(b*LL + qbase + r)*EE + e];
    }

    // ---- phase 1: S_tile[32][512] = q_tile @ k^T / sqrt(32), into smem ----
    int ql4 = tid >> 4, kg = tid & 15;
    const float sc = 0.17677669529663687f; // 1/sqrt(32)
    for (int kt = 0; kt < 8; kt++) {
        __syncthreads();
        for (int i = tid; i < 64*EE; i += 512) {
            int r = i >> 5, e = i & 31;
            kbuf[r*33+e] = g_k[(b*LL + kt*64 + r)*EE + e];
        }
        __syncthreads();
        float a0 = 0.f, a1 = 0.f, a2 = 0.f, a3 = 0.f;
        #pragma unroll
        for (int e = 0; e < EE; e++) {
            float qv = q_s[ql4*33+e];
            a0 += qv * kbuf[(kg*4+0)*33+e];
            a1 += qv * kbuf[(kg*4+1)*33+e];
            a2 += qv * kbuf[(kg*4+2)*33+e];
            a3 += qv * kbuf[(kg*4+3)*33+e];
        }
        float4 o = make_float4(a0*sc, a1*sc, a2*sc, a3*sc);
        *(float4*)&S_s[ql4*LL + kt*64 + kg*4] = o;
    }
    __syncthreads();

    // ---- phase 2: bucketed online softmax (warp per (ql,c) task) ----
    int wid = tid >> 5, lane = tid & 31;
    for (int task = wid; task < 32*KK; task += 16) {
        int ql = task >> 4, c = task & 15;
        int q = qbase + ql;
        int cnt = cnt_s[c];
        // logit = s if k <= q+1 else 0 (W_OFF=1): future positions with
        // matching mark contribute exp(0) — matches reference exactly.
        float m = -1e30f, se = 0.f, sv = 0.f;
        for (int i = lane; i < cnt; i += 32) {
            int   kk = g_bidx[(b*KK+c)*LL + i];
            float s  = S_s[ql*LL + kk];
            float lg = (kk <= q+1) ? s : 0.f;
            float v  = val_s[kk];
            float nm = fmaxf(m, lg);
            float ea = __expf(m - nm), eb = __expf(lg - nm);
            se = se*ea + eb;
            sv = sv*ea + eb*v;
            m = nm;
        }
        #pragma unroll
        for (int off = 16; off > 0; off >>= 1) {
            float mo  = __shfl_xor_sync(0xffffffffu, m,  off);
            float seo = __shfl_xor_sync(0xffffffffu, se, off);
            float svo = __shfl_xor_sync(0xffffffffu, sv, off);
            float nm = fmaxf(m, mo);
            float ea = __expf(m - nm), eb = __expf(mo - nm);
            se = se*ea + seo*eb;
            sv = sv*ea + svo*eb;
            m = nm;
        }
        if (lane == 0) x_s[ql*KK+c] = (se > 0.f) ? sv/se : 0.f;
    }
    __syncthreads();

    // ---- phase 3: GI[b,q,g] = cc[g] + sum_c M2[g][c] * x[q][c] ----
    for (int o = tid; o < 32*GG; o += 512) {
        int ql = o / GG, g = o % GG;
        float acc = cc_s[g];
        #pragma unroll
        for (int c = 0; c < KK; c++) acc += M2_s[g*17+c] * x_s[ql*KK+c];
        g_GI[((size_t)(b*LL) + qbase + ql)*GG + g] = acc;
    }
}

// -------- kernel 3: GRU scan — f32x2 matvec + tanh.approx gates --------
__global__ void __launch_bounds__(GG) k_gru(const float* __restrict__ W_hh,
                                            const float* __restrict__ b_hh,
                                            float* __restrict__ out) {
    int b = blockIdx.x, t = threadIdx.x;   // 192 threads: one gate row each
    __shared__ __align__(16) float h_s[NHH];
    __shared__ float gh_s[GG];

    // W_hh row packed as 32 f32x2 values (64 regs)
    unsigned long long w2[32];
    {
        const ulonglong2* wp = (const ulonglong2*)(W_hh + (size_t)t*NHH);
        #pragma unroll
        for (int i = 0; i < 16; i++) {
            ulonglong2 v = wp[i];
            w2[2*i]   = v.x;   // (w[4i],   w[4i+1])
            w2[2*i+1] = v.y;   // (w[4i+2], w[4i+3])
        }
    }
    float bh = b_hh[t];
    if (t < NHH) h_s[t] = 0.f;

    float g0 = 0.f, g1 = 0.f, g2 = 0.f;    // current-step input gates
    if (t < NHH) {
        const float* gp = g_GI + (size_t)b*LL*GG;
        g0 = gp[t]; g1 = gp[t+NHH]; g2 = gp[t+2*NHH];
    }
    unsigned haddr = (unsigned)__cvta_generic_to_shared(h_s);
    __syncthreads();

    for (int l = 0; l < LL; l++) {
        // prefetch next step's input gates (L2 latency hides under matvec)
        float n0 = 0.f, n1 = 0.f, n2 = 0.f;
        if (t < NHH && l+1 < LL) {
            const float* gp = g_GI + ((size_t)b*LL + l + 1)*GG;
            n0 = gp[t]; n1 = gp[t+NHH]; n2 = gp[t+2*NHH];
        }
        // gh[t] = W_hh[t,:] . h  -- 32 packed FFMA2, 4 accumulator chains
        unsigned long long a0 = 0ull, a1 = 0ull, a2 = 0ull, a3 = 0ull;
        #pragma unroll
        for (int i = 0; i < 16; i++) {
            unsigned long long hx, hy;
            asm volatile("ld.shared.v2.u64 {%0, %1}, [%2];"
                         : "=l"(hx), "=l"(hy) : "r"(haddr + i*16));
            if (i & 1) { FMA2(a2, w2[2*i], hx); FMA2(a3, w2[2*i+1], hy); }
            else       { FMA2(a0, w2[2*i], hx); FMA2(a1, w2[2*i+1], hy); }
        }
        float s0 = __uint_as_float((unsigned)a0) + __uint_as_float((unsigned)(a0 >> 32));
        float s1 = __uint_as_float((unsigned)a1) + __uint_as_float((unsigned)(a1 >> 32));
        float s2 = __uint_as_float((unsigned)a2) + __uint_as_float((unsigned)(a2 >> 32));
        float s3 = __uint_as_float((unsigned)a3) + __uint_as_float((unsigned)(a3 >> 32));
        gh_s[t] = bh + (s0 + s1) + (s2 + s3);
        __syncthreads();
        if (t < NHH) {
            float hr = gh_s[t], hz = gh_s[t+NHH], hn = gh_s[t+2*NHH];
            float r = 0.5f * tanh_fast(0.5f * (g0 + hr)) + 0.5f;  // sigmoid
            float z = 0.5f * tanh_fast(0.5f * (g1 + hz)) + 0.5f;  // sigmoid
            float n = tanh_fast(g2 + r*hn);
            float hnew = (1.f - z)*n + z*h_s[t];
            out[((size_t)b*LL + l)*NHH + t] = hnew;
            h_s[t] = hnew;
            g0 = n0; g1 = n1; g2 = n2;
        }
        __syncthreads();
    }
}

// -------- launch --------
extern "C" void kernel_launch(void* const* d_in, const int* in_sizes, int n_in,
                              void* d_out, int out_size) {
    const float* ts   = (const float*)d_in[0];
    const float* val  = (const float*)d_in[1];
    const int*   mark = (const int*)  d_in[2];
    const float* npm  = (const float*)d_in[3];
    const float* Wl   = (const float*)d_in[4];
    const float* bl   = (const float*)d_in[5];
    const float* Wp   = (const float*)d_in[6];
    const float* bp   = (const float*)d_in[7];
    const float* Wq   = (const float*)d_in[8];
    const float* bq   = (const float*)d_in[9];
    const float* Wk   = (const float*)d_in[10];
    const float* bk   = (const float*)d_in[11];
    const float* Wo   = (const float*)d_in[12];
    const float* bo   = (const float*)d_in[13];
    const float* W_ih = (const float*)d_in[14];
    const float* W_hh = (const float*)d_in[15];
    const float* b_ih = (const float*)d_in[16];
    const float* b_hh = (const float*)d_in[17];
    float* out = (float*)d_out;

    static int att_attr_set = 0;
    if (!att_attr_set) {
        cudaFuncSetAttribute(k_att2, cudaFuncAttributeMaxDynamicSharedMemorySize,
                             SMEM_ATT_BYTES);
        att_attr_set = 1;
    }

    k_setup<<<17, 512>>>(ts, Wl, bl, Wp, bp, Wq, bq, Wk, bk,
                         mark, npm, W_ih, Wo, b_ih, bo);
    k_att2 <<<dim3(16,8), 512, SMEM_ATT_BYTES>>>(val);
    k_gru  <<<8, 192>>>(W_hh, b_hh, out);
}

// round 5
// speedup vs baseline: 1.1139x; 1.0506x over previous
#include <cuda_runtime.h>
#include <math.h>

#define BB  8
#define LL  512
#define KK  16
#define EE  32
#define NHH 64
#define GG  192

// -------- scratch (static device globals; no runtime allocation) --------
__device__ float g_q[BB*LL*EE];
__device__ float g_k[BB*LL*EE];
__device__ int   g_bcnt[BB*KK];
__device__ int   g_bidx[BB*KK*LL];   // per (b,c) ordered list of positions
__device__ float g_M2[GG*KK];        // W_ih @ Wo   (192 x 16)
__device__ float g_cc[GG];           // W_ih @ bo + b_ih
__device__ float g_GI[BB*LL*GG];     // precomputed input gates

__device__ __forceinline__ float tanh_fast(float x) {
    float y;
    asm("tanh.approx.f32 %0, %1;" : "=f"(y) : "f"(x));
    return y;
}
#define FMA2(acc, x, y) \
    asm("fma.rn.f32x2 %0, %1, %2, %0;" : "+l"(acc) : "l"(x), "l"(y))

// -------- kernel 1: setup (key_emb + Q/K projection, Wo fold) --------
// blocks 0..31: projection, block (b*4 + quarter); block 32: M2 fold.
__global__ void __launch_bounds__(512) k_setup(
        const float* __restrict__ ts,
        const float* __restrict__ Wl, const float* __restrict__ bl,
        const float* __restrict__ Wp, const float* __restrict__ bp,
        const float* __restrict__ Wq, const float* __restrict__ bq,
        const float* __restrict__ Wk, const float* __restrict__ bk,
        const float* __restrict__ W_ih, const float* __restrict__ Wo,
        const float* __restrict__ b_ih, const float* __restrict__ bo) {
    int blk = blockIdx.x, tid = threadIdx.x;
    if (blk < 32) {
        __shared__ float ke_s[128*33];
        __shared__ float wq_s[EE*33], wk_s[EE*33];
        __shared__ float sWp[EE], sbp[EE];
        __shared__ float sWl, sbl;
        int b = blk >> 2, rbase = (blk & 3) * 128;

        // stage weights transposed-padded: wq_s[e*33+j] = Wq[e][j]
        for (int i = tid; i < EE*EE; i += 512) {
            int e = i >> 5, j = i & 31;
            wq_s[e*33+j] = Wq[i];
            wk_s[e*33+j] = Wk[i];
        }
        if (tid < EE-1) { sWp[tid] = Wp[tid]; sbp[tid] = bp[tid]; }
        if (tid == 0)   { sWl = Wl[0]; sbl = bl[0]; }
        __syncthreads();

        // phase A: key_emb for 128 rows into smem
        for (int idx = tid; idx < 128*EE; idx += 512) {
            int r = idx >> 5, i = idx & 31;
            float t = ts[b*LL + rbase + r];
            float v = (i == 0) ? fmaf(t, sWl, sbl)
                               : sinf(fmaf(t, sWp[i-1], sbp[i-1]));
            ke_s[r*33 + i] = v;
        }
        __syncthreads();

        // phase B: thread (r0,e) — weight columns in REGISTERS, ke broadcast
        int e = tid & 31, r0 = tid >> 5;   // warp <-> one r0 (ke reads uniform)
        float wq[EE], wk[EE];
        #pragma unroll
        for (int j = 0; j < EE; j++) { wq[j] = wq_s[e*33+j]; wk[j] = wk_s[e*33+j]; }
        float bqv = __ldg(&bq[e]), bkv = __ldg(&bk[e]);
        #pragma unroll
        for (int pass = 0; pass < 8; pass++) {
            int r = pass*16 + r0;
            float aq = bqv, ak = bkv;
            #pragma unroll
            for (int j = 0; j < EE; j++) {
                float kv = ke_s[r*33+j];
                aq = fmaf(wq[j], kv, aq);
                ak = fmaf(wk[j], kv, ak);
            }
            int row = b*LL + rbase + r;
            g_q[row*EE + e] = aq;
            g_k[row*EE + e] = ak;
        }
    } else if (tid < GG) {
        // ---- fold Wo into W_ih: M2 = W_ih@Wo, cc = W_ih@bo + b_ih ----
        int g = tid;
        float wrow[NHH];
        #pragma unroll
        for (int o = 0; o < NHH; o++) wrow[o] = W_ih[g*NHH+o];
        float cc = b_ih[g];
        #pragma unroll
        for (int o = 0; o < NHH; o++) cc += wrow[o] * bo[o];
        g_cc[g] = cc;
        for (int c = 0; c < KK; c++) {
            float a = 0.f;
            #pragma unroll
            for (int o = 0; o < NHH; o++) a += wrow[o] * Wo[o*KK+c];
            g_M2[g*KK+c] = a;
        }
    }
}

// -------- kernel 2: bucket build (warp per category, ballot compaction) ----
__global__ void k_bucket(const int* __restrict__ mark, const float* __restrict__ npm) {
    int b = blockIdx.x;
    int c = threadIdx.x >> 5, lane = threadIdx.x & 31;  // 16 warps = 16 cats
    int base = 0;
    for (int ch = 0; ch < LL/32; ch++) {
        int k = ch*32 + lane;
        int   mk = mark[b*LL+k];
        float np = npm[b*LL+k];
        bool hit = (mk == c+1) && (np > 0.f);
        unsigned m = __ballot_sync(0xffffffffu, hit);
        if (hit) g_bidx[(b*KK+c)*LL + base + __popc(m & ((1u<<lane)-1u))] = k;
        base += __popc(m);
    }
    if (lane == 0) g_bcnt[b*KK+c] = base;
}

// -------- kernel 3: fused scores(GEMM-in-smem) + bucketed softmax + GI ----
#define SOFF_S    0            // 32*512  score tile
#define SOFF_KB   16384        // 64*33   k staging
#define SOFF_Q    18496        // 32*33
#define SOFF_VAL  19552        // 512
#define SOFF_X    20064        // 512
#define SOFF_M2   20576        // 192*17
#define SOFF_CC   23840        // 192
#define SOFF_CNT  24032        // 16 ints
#define SMEM_ATT_BYTES (24032*4 + 16*4)

__global__ void k_att2(const float* __restrict__ val) {
    extern __shared__ float sm[];
    float* S_s   = sm + SOFF_S;
    float* kbuf  = sm + SOFF_KB;
    float* q_s   = sm + SOFF_Q;
    float* val_s = sm + SOFF_VAL;
    float* x_s   = sm + SOFF_X;
    float* M2_s  = sm + SOFF_M2;
    float* cc_s  = sm + SOFF_CC;
    int*   cnt_s = (int*)(sm + SOFF_CNT);

    int tid = threadIdx.x;                 // 512 threads = 16 warps
    int b = blockIdx.y;
    int qbase = blockIdx.x * 32;

    for (int i = tid; i < LL; i += 512) val_s[i] = val[b*LL+i];
    if (tid < KK) cnt_s[tid] = g_bcnt[b*KK+tid];
    for (int i = tid; i < GG*KK; i += 512) {
        int g = i >> 4, c = i & 15;
        M2_s[g*17+c] = g_M2[i];
    }
    if (tid < GG) cc_s[tid] = g_cc[tid];
    for (int i = tid; i < 32*EE; i += 512) {
        int r = i >> 5, e = i & 31;
        q_s[r*33+e] = g_q[(b*LL + qbase + r)*EE + e];
    }

    // ---- phase 1: S_tile[32][512] = q_tile @ k^T / sqrt(32), into smem ----
    int ql4 = tid >> 4, kg = tid & 15;
    const float sc = 0.17677669529663687f; // 1/sqrt(32)
    for (int kt = 0; kt < 8; kt++) {
        __syncthreads();
        for (int i = tid; i < 64*EE; i += 512) {
            int r = i >> 5, e = i & 31;
            kbuf[r*33+e] = g_k[(b*LL + kt*64 + r)*EE + e];
        }
        __syncthreads();
        float a0 = 0.f, a1 = 0.f, a2 = 0.f, a3 = 0.f;
        #pragma unroll
        for (int e = 0; e < EE; e++) {
            float qv = q_s[ql4*33+e];
            a0 += qv * kbuf[(kg*4+0)*33+e];
            a1 += qv * kbuf[(kg*4+1)*33+e];
            a2 += qv * kbuf[(kg*4+2)*33+e];
            a3 += qv * kbuf[(kg*4+3)*33+e];
        }
        float4 o = make_float4(a0*sc, a1*sc, a2*sc, a3*sc);
        *(float4*)&S_s[ql4*LL + kt*64 + kg*4] = o;
    }
    __syncthreads();

    // ---- phase 2: bucketed online softmax (warp per (ql,c) task) ----
    int wid = tid >> 5, lane = tid & 31;
    for (int task = wid; task < 32*KK; task += 16) {
        int ql = task >> 4, c = task & 15;
        int q = qbase + ql;
        int cnt = cnt_s[c];
        // logit = s if k <= q+1 else 0 (W_OFF=1): future positions with
        // matching mark contribute exp(0) — matches reference exactly.
        float m = -1e30f, se = 0.f, sv = 0.f;
        for (int i = lane; i < cnt; i += 32) {
            int   kk = g_bidx[(b*KK+c)*LL + i];
            float s  = S_s[ql*LL + kk];
            float lg = (kk <= q+1) ? s : 0.f;
            float v  = val_s[kk];
            float nm = fmaxf(m, lg);
            float ea = __expf(m - nm), eb = __expf(lg - nm);
            se = se*ea + eb;
            sv = sv*ea + eb*v;
            m = nm;
        }
        #pragma unroll
        for (int off = 16; off > 0; off >>= 1) {
            float mo  = __shfl_xor_sync(0xffffffffu, m,  off);
            float seo = __shfl_xor_sync(0xffffffffu, se, off);
            float svo = __shfl_xor_sync(0xffffffffu, sv, off);
            float nm = fmaxf(m, mo);
            float ea = __expf(m - nm), eb = __expf(mo - nm);
            se = se*ea + seo*eb;
            sv = sv*ea + svo*eb;
            m = nm;
        }
        if (lane == 0) x_s[ql*KK+c] = (se > 0.f) ? sv/se : 0.f;
    }
    __syncthreads();

    // ---- phase 3: GI[b,q,g] = cc[g] + sum_c M2[g][c] * x[q][c] ----
    for (int o = tid; o < 32*GG; o += 512) {
        int ql = o / GG, g = o % GG;
        float acc = cc_s[g];
        #pragma unroll
        for (int c = 0; c < KK; c++) acc += M2_s[g*17+c] * x_s[ql*KK+c];
        g_GI[((size_t)(b*LL) + qbase + ql)*GG + g] = acc;
    }
}

// -------- kernel 4: GRU scan — f32x2 matvec + tanh.approx gates --------
__global__ void __launch_bounds__(GG) k_gru(const float* __restrict__ W_hh,
                                            const float* __restrict__ b_hh,
                                            float* __restrict__ out) {
    int b = blockIdx.x, t = threadIdx.x;   // 192 threads: one gate row each
    __shared__ __align__(16) float h_s[NHH];
    __shared__ float gh_s[GG];

    // W_hh row packed as 32 f32x2 values (64 regs)
    unsigned long long w2[32];
    {
        const ulonglong2* wp = (const ulonglong2*)(W_hh + (size_t)t*NHH);
        #pragma unroll
        for (int i = 0; i < 16; i++) {
            ulonglong2 v = wp[i];
            w2[2*i]   = v.x;   // (w[4i],   w[4i+1])
            w2[2*i+1] = v.y;   // (w[4i+2], w[4i+3])
        }
    }
    float bh = b_hh[t];
    float hown = 0.f;                      // h[t] for t < NHH (register copy)
    if (t < NHH) h_s[t] = 0.f;

    float g0 = 0.f, g1 = 0.f, g2 = 0.f;    // current-step input gates
    if (t < NHH) {
        const float* gp = g_GI + (size_t)b*LL*GG;
        g0 = gp[t]; g1 = gp[t+NHH]; g2 = gp[t+2*NHH];
    }
    unsigned haddr = (unsigned)__cvta_generic_to_shared(h_s);
    __syncthreads();

    for (int l = 0; l < LL; l++) {
        // prefetch next step's input gates (L2 latency hides under matvec)
        float n0 = 0.f, n1 = 0.f, n2 = 0.f;
        if (t < NHH && l+1 < LL) {
            const float* gp = g_GI + ((size_t)b*LL + l + 1)*GG;
            n0 = gp[t]; n1 = gp[t+NHH]; n2 = gp[t+2*NHH];
        }
        // gh[t] = W_hh[t,:] . h  -- 32 packed FFMA2, 4 accumulator chains
        unsigned long long a0 = 0ull, a1 = 0ull, a2 = 0ull, a3 = 0ull;
        #pragma unroll
        for (int i = 0; i < 16; i++) {
            unsigned long long hx, hy;
            asm volatile("ld.shared.v2.u64 {%0, %1}, [%2];"
                         : "=l"(hx), "=l"(hy) : "r"(haddr + i*16));
            if (i & 1) { FMA2(a2, w2[2*i], hx); FMA2(a3, w2[2*i+1], hy); }
            else       { FMA2(a0, w2[2*i], hx); FMA2(a1, w2[2*i+1], hy); }
        }
        float s0 = __uint_as_float((unsigned)a0) + __uint_as_float((unsigned)(a0 >> 32));
        float s1 = __uint_as_float((unsigned)a1) + __uint_as_float((unsigned)(a1 >> 32));
        float s2 = __uint_as_float((unsigned)a2) + __uint_as_float((unsigned)(a2 >> 32));
        float s3 = __uint_as_float((unsigned)a3) + __uint_as_float((unsigned)(a3 >> 32));
        gh_s[t] = bh + (s0 + s1) + (s2 + s3);
        __syncthreads();
        if (t < NHH) {
            float hr = gh_s[t], hz = gh_s[t+NHH], hn = gh_s[t+2*NHH];
            float r = 0.5f * tanh_fast(0.5f * (g0 + hr)) + 0.5f;  // sigmoid
            float z = 0.5f * tanh_fast(0.5f * (g1 + hz)) + 0.5f;  // sigmoid
            float n = tanh_fast(g2 + r*hn);
            float hnew = (1.f - z)*n + z*hown;
            out[((size_t)b*LL + l)*NHH + t] = hnew;
            h_s[t] = hnew;
            hown = hnew;
            g0 = n0; g1 = n1; g2 = n2;
        }
        __syncthreads();
    }
}

// -------- launch --------
extern "C" void kernel_launch(void* const* d_in, const int* in_sizes, int n_in,
                              void* d_out, int out_size) {
    const float* ts   = (const float*)d_in[0];
    const float* val  = (const float*)d_in[1];
    const int*   mark = (const int*)  d_in[2];
    const float* npm  = (const float*)d_in[3];
    const float* Wl   = (const float*)d_in[4];
    const float* bl   = (const float*)d_in[5];
    const float* Wp   = (const float*)d_in[6];
    const float* bp   = (const float*)d_in[7];
    const float* Wq   = (const float*)d_in[8];
    const float* bq   = (const float*)d_in[9];
    const float* Wk   = (const float*)d_in[10];
    const float* bk   = (const float*)d_in[11];
    const float* Wo   = (const float*)d_in[12];
    const float* bo   = (const float*)d_in[13];
    const float* W_ih = (const float*)d_in[14];
    const float* W_hh = (const float*)d_in[15];
    const float* b_ih = (const float*)d_in[16];
    const float* b_hh = (const float*)d_in[17];
    float* out = (float*)d_out;

    static int att_attr_set = 0;
    if (!att_attr_set) {
        cudaFuncSetAttribute(k_att2, cudaFuncAttributeMaxDynamicSharedMemorySize,
                             SMEM_ATT_BYTES);
        att_attr_set = 1;
    }

    k_setup <<<33, 512>>>(ts, Wl, bl, Wp, bp, Wq, bq, Wk, bk,
                          W_ih, Wo, b_ih, bo);
    k_bucket<<<8, 512>>>(mark, npm);
    k_att2  <<<dim3(16,8), 512, SMEM_ATT_BYTES>>>(val);
    k_gru   <<<8, 192>>>(W_hh, b_hh, out);
}

// round 6
// speedup vs baseline: 2.1289x; 1.9113x over previous
#include <cuda_runtime.h>
#include <math.h>

#define BB  8
#define LL  512
#define KK  16
#define EE  32
#define NHH 64
#define GG  192
#define CH      16           // GRU: steps per GI prefetch chunk
#define NCHUNK  (LL/CH)      // 32

// -------- scratch (static device globals; no runtime allocation) --------
__device__ float g_q[BB*LL*EE];
__device__ float g_k[BB*LL*EE];
__device__ int   g_bcnt[BB*KK];
__device__ int   g_bidx[BB*KK*LL];   // per (b,c) ordered list of positions
__device__ float g_M2[GG*KK];        // W_ih @ Wo   (192 x 16)
__device__ float g_cc[GG];           // W_ih @ bo + b_ih
__device__ float g_GI[BB*LL*GG];     // precomputed input gates

__device__ __forceinline__ float tanh_fast(float x) {
    float y;
    asm("tanh.approx.f32 %0, %1;" : "=f"(y) : "f"(x));
    return y;
}
#define FMA2(acc, x, y) \
    asm("fma.rn.f32x2 %0, %1, %2, %0;" : "+l"(acc) : "l"(x), "l"(y))
__device__ __forceinline__ float f2lo(unsigned long long v) {
    return __uint_as_float((unsigned)v);
}
__device__ __forceinline__ float f2hi(unsigned long long v) {
    return __uint_as_float((unsigned)(v >> 32));
}

// -------- kernel 1: setup (proj blocks 0-31, fold block 32, buckets 33-40) --
__global__ void __launch_bounds__(512) k_setup(
        const float* __restrict__ ts,
        const float* __restrict__ Wl, const float* __restrict__ bl,
        const float* __restrict__ Wp, const float* __restrict__ bp,
        const float* __restrict__ Wq, const float* __restrict__ bq,
        const float* __restrict__ Wk, const float* __restrict__ bk,
        const float* __restrict__ W_ih, const float* __restrict__ Wo,
        const float* __restrict__ b_ih, const float* __restrict__ bo,
        const int*   __restrict__ mark, const float* __restrict__ npm) {
    int blk = blockIdx.x, tid = threadIdx.x;
    if (blk < 32) {
        __shared__ float ke_s[128*33];
        __shared__ float wq_s[EE*33], wk_s[EE*33];
        __shared__ float sWp[EE], sbp[EE];
        __shared__ float sWl, sbl;
        int b = blk >> 2, rbase = (blk & 3) * 128;

        for (int i = tid; i < EE*EE; i += 512) {
            int e = i >> 5, j = i & 31;
            wq_s[e*33+j] = Wq[i];
            wk_s[e*33+j] = Wk[i];
        }
        if (tid < EE-1) { sWp[tid] = Wp[tid]; sbp[tid] = bp[tid]; }
        if (tid == 0)   { sWl = Wl[0]; sbl = bl[0]; }
        __syncthreads();

        for (int idx = tid; idx < 128*EE; idx += 512) {
            int r = idx >> 5, i = idx & 31;
            float t = ts[b*LL + rbase + r];
            float v = (i == 0) ? fmaf(t, sWl, sbl)
                               : sinf(fmaf(t, sWp[i-1], sbp[i-1]));
            ke_s[r*33 + i] = v;
        }
        __syncthreads();

        int e = tid & 31, r0 = tid >> 5;   // warp <-> one r0 (ke reads uniform)
        float wq[EE], wk[EE];
        #pragma unroll
        for (int j = 0; j < EE; j++) { wq[j] = wq_s[e*33+j]; wk[j] = wk_s[e*33+j]; }
        float bqv = __ldg(&bq[e]), bkv = __ldg(&bk[e]);
        #pragma unroll
        for (int pass = 0; pass < 8; pass++) {
            int r = pass*16 + r0;
            float aq = bqv, ak = bkv;
            #pragma unroll
            for (int j = 0; j < EE; j++) {
                float kv = ke_s[r*33+j];
                aq = fmaf(wq[j], kv, aq);
                ak = fmaf(wk[j], kv, ak);
            }
            int row = b*LL + rbase + r;
            g_q[row*EE + e] = aq;
            g_k[row*EE + e] = ak;
        }
    } else if (blk == 32) {
        if (tid < GG) {
            int g = tid;
            float wrow[NHH];
            #pragma unroll
            for (int o = 0; o < NHH; o++) wrow[o] = W_ih[g*NHH+o];
            float cc = b_ih[g];
            #pragma unroll
            for (int o = 0; o < NHH; o++) cc += wrow[o] * bo[o];
            g_cc[g] = cc;
            for (int c = 0; c < KK; c++) {
                float a = 0.f;
                #pragma unroll
                for (int o = 0; o < NHH; o++) a += wrow[o] * Wo[o*KK+c];
                g_M2[g*KK+c] = a;
            }
        }
    } else {
        // ---- bucket build: warp per category, ballot compaction ----
        int b = blk - 33;
        int c = tid >> 5, lane = tid & 31;    // 16 warps = 16 categories
        int base = 0;
        for (int ch = 0; ch < LL/32; ch++) {
            int k = ch*32 + lane;
            int   mk = mark[b*LL+k];
            float np = npm[b*LL+k];
            bool hit = (mk == c+1) && (np > 0.f);
            unsigned m = __ballot_sync(0xffffffffu, hit);
            if (hit) g_bidx[(b*KK+c)*LL + base + __popc(m & ((1u<<lane)-1u))] = k;
            base += __popc(m);
        }
        if (lane == 0) g_bcnt[b*KK+c] = base;
    }
}

// -------- kernel 2: fused scores(GEMM-in-smem) + bucketed softmax + GI ----
#define SOFF_S    0            // 32*512  score tile
#define SOFF_KB   16384        // 64*33   k staging
#define SOFF_Q    18496        // 32*33
#define SOFF_VAL  19552        // 512
#define SOFF_X    20064        // 512
#define SOFF_M2   20576        // 192*17
#define SOFF_CC   23840        // 192
#define SOFF_CNT  24032        // 16 ints
#define SMEM_ATT_BYTES (24032*4 + 16*4)

__global__ void k_att2(const float* __restrict__ val) {
    extern __shared__ float sm[];
    float* S_s   = sm + SOFF_S;
    float* kbuf  = sm + SOFF_KB;
    float* q_s   = sm + SOFF_Q;
    float* val_s = sm + SOFF_VAL;
    float* x_s   = sm + SOFF_X;
    float* M2_s  = sm + SOFF_M2;
    float* cc_s  = sm + SOFF_CC;
    int*   cnt_s = (int*)(sm + SOFF_CNT);

    int tid = threadIdx.x;                 // 512 threads = 16 warps
    int b = blockIdx.y;
    int qbase = blockIdx.x * 32;

    for (int i = tid; i < LL; i += 512) val_s[i] = val[b*LL+i];
    if (tid < KK) cnt_s[tid] = g_bcnt[b*KK+tid];
    for (int i = tid; i < GG*KK; i += 512) {
        int g = i >> 4, c = i & 15;
        M2_s[g*17+c] = g_M2[i];
    }
    if (tid < GG) cc_s[tid] = g_cc[tid];
    for (int i = tid; i < 32*EE; i += 512) {
        int r = i >> 5, e = i & 31;
        q_s[r*33+e] = g_q[(b*LL + qbase + r)*EE + e];
    }

    // ---- phase 1: S_tile[32][512] = q_tile @ k^T / sqrt(32), into smem ----
    int ql4 = tid >> 4, kg = tid & 15;
    const float sc = 0.17677669529663687f; // 1/sqrt(32)
    for (int kt = 0; kt < 8; kt++) {
        __syncthreads();
        for (int i = tid; i < 64*EE; i += 512) {
            int r = i >> 5, e = i & 31;
            kbuf[r*33+e] = g_k[(b*LL + kt*64 + r)*EE + e];
        }
        __syncthreads();
        float a0 = 0.f, a1 = 0.f, a2 = 0.f, a3 = 0.f;
        #pragma unroll
        for (int e = 0; e < EE; e++) {
            float qv = q_s[ql4*33+e];
            a0 += qv * kbuf[(kg*4+0)*33+e];
            a1 += qv * kbuf[(kg*4+1)*33+e];
            a2 += qv * kbuf[(kg*4+2)*33+e];
            a3 += qv * kbuf[(kg*4+3)*33+e];
        }
        float4 o = make_float4(a0*sc, a1*sc, a2*sc, a3*sc);
        *(float4*)&S_s[ql4*LL + kt*64 + kg*4] = o;
    }
    __syncthreads();

    // ---- phase 2: bucketed online softmax (warp per (ql,c) task) ----
    int wid = tid >> 5, lane = tid & 31;
    for (int task = wid; task < 32*KK; task += 16) {
        int ql = task >> 4, c = task & 15;
        int q = qbase + ql;
        int cnt = cnt_s[c];
        // logit = s if k <= q+1 else 0 (W_OFF=1): future positions with
        // matching mark contribute exp(0) — matches reference exactly.
        float m = -1e30f, se = 0.f, sv = 0.f;
        for (int i = lane; i < cnt; i += 32) {
            int   kk = g_bidx[(b*KK+c)*LL + i];
            float s  = S_s[ql*LL + kk];
            float lg = (kk <= q+1) ? s : 0.f;
            float v  = val_s[kk];
            float nm = fmaxf(m, lg);
            float ea = __expf(m - nm), eb = __expf(lg - nm);
            se = se*ea + eb;
            sv = sv*ea + eb*v;
            m = nm;
        }
        #pragma unroll
        for (int off = 16; off > 0; off >>= 1) {
            float mo  = __shfl_xor_sync(0xffffffffu, m,  off);
            float seo = __shfl_xor_sync(0xffffffffu, se, off);
            float svo = __shfl_xor_sync(0xffffffffu, sv, off);
            float nm = fmaxf(m, mo);
            float ea = __expf(m - nm), eb = __expf(mo - nm);
            se = se*ea + seo*eb;
            sv = sv*ea + svo*eb;
            m = nm;
        }
        if (lane == 0) x_s[ql*KK+c] = (se > 0.f) ? sv/se : 0.f;
    }
    __syncthreads();

    // ---- phase 3: GI[b,q,g] = cc[g] + sum_c M2[g][c] * x[q][c] ----
    for (int o = tid; o < 32*GG; o += 512) {
        int ql = o / GG, g = o % GG;
        float acc = cc_s[g];
        #pragma unroll
        for (int c = 0; c < KK; c++) acc += M2_s[g*17+c] * x_s[ql*KK+c];
        g_GI[((size_t)(b*LL) + qbase + ql)*GG + g] = acc;
    }
}

// -------- kernel 3: GRU scan, one-barrier-per-step lane-pair design --------
// 128 threads = 4 warps. thread (u = tid>>1, half = tid&1) computes the
// half-k partial of ALL THREE gate rows (u, 64+u, 128+u); cross-half sum via
// shfl.bfly(1) (intra-warp, barrier-free). Gates computed redundantly by both
// halves; half 0 publishes hnew. ONE __syncthreads per step.
// GI staged into smem via cp.async, double-buffered 16-step chunks.
__global__ void __launch_bounds__(128) k_gru2(const float* __restrict__ W_hh,
                                              const float* __restrict__ b_hh,
                                              float* __restrict__ out) {
    int b = blockIdx.x, tid = threadIdx.x;
    int u = tid >> 1, half = tid & 1;
    __shared__ __align__(16) float h_s[NHH];
    __shared__ __align__(16) float gi_s[2][CH*GG];

    // weights: rows u / 64+u / 128+u, k-slice [half*32, half*32+32), as f32x2
    unsigned long long wr[16], wz[16], wn[16];
    {
        const ulonglong2* r2 = (const ulonglong2*)(W_hh + (size_t)u*NHH       + half*32);
        const ulonglong2* z2 = (const ulonglong2*)(W_hh + (size_t)(64+u)*NHH  + half*32);
        const ulonglong2* n2 = (const ulonglong2*)(W_hh + (size_t)(128+u)*NHH + half*32);
        #pragma unroll
        for (int i = 0; i < 8; i++) {
            ulonglong2 a = r2[i]; wr[2*i] = a.x; wr[2*i+1] = a.y;
            ulonglong2 c = z2[i]; wz[2*i] = c.x; wz[2*i+1] = c.y;
            ulonglong2 d = n2[i]; wn[2*i] = d.x; wn[2*i+1] = d.y;
        }
    }
    float br = b_hh[u], bz = b_hh[64+u], bn = b_hh[128+u];
    float h_old = 0.f;
    if (tid < NHH) h_s[tid] = 0.f;

    unsigned haddr = (unsigned)__cvta_generic_to_shared(h_s) + half*128;
    unsigned gibase = (unsigned)__cvta_generic_to_shared(gi_s);
    const float* gi_src = g_GI + (size_t)b*LL*GG;
    float* out_b = out + (size_t)b*LL*NHH;

    // prologue: prefetch chunks 0 and 1
    #pragma unroll
    for (int cpre = 0; cpre < 2; cpre++) {
        #pragma unroll
        for (int i = 0; i < 6; i++) {
            int unit = tid + i*128;               // 768 x 16B per chunk
            asm volatile("cp.async.ca.shared.global [%0], [%1], 16;"
                :: "r"(gibase + cpre*(CH*GG*4) + unit*16),
                   "l"(gi_src + cpre*CH*GG + unit*4));
        }
        asm volatile("cp.async.commit_group;");
    }
    asm volatile("cp.async.wait_group 1;");
    __syncthreads();

    for (int c = 0; c < NCHUNK; c++) {
        const float* gi = gi_s[c & 1];
        for (int s = 0; s < CH; s++) {
            // half-matvec: 8x LDS.128 of h-half, 48 FMA2 over 6 chains
            unsigned long long ar0=0ull, ar1=0ull, az0=0ull, az1=0ull,
                               an0=0ull, an1=0ull;
            #pragma unroll
            for (int i = 0; i < 8; i++) {
                unsigned long long hx, hy;
                asm volatile("ld.shared.v2.u64 {%0, %1}, [%2];"
                             : "=l"(hx), "=l"(hy) : "r"(haddr + i*16));
                FMA2(ar0, wr[2*i], hx); FMA2(ar1, wr[2*i+1], hy);
                FMA2(az0, wz[2*i], hx); FMA2(az1, wz[2*i+1], hy);
                FMA2(an0, wn[2*i], hx); FMA2(an1, wn[2*i+1], hy);
            }
            float sr = (f2lo(ar0)+f2hi(ar0)) + (f2lo(ar1)+f2hi(ar1));
            float sz = (f2lo(az0)+f2hi(az0)) + (f2lo(az1)+f2hi(az1));
            float sn = (f2lo(an0)+f2hi(an0)) + (f2lo(an1)+f2hi(an1));
            sr += __shfl_xor_sync(0xffffffffu, sr, 1);
            sz += __shfl_xor_sync(0xffffffffu, sz, 1);
            sn += __shfl_xor_sync(0xffffffffu, sn, 1);

            float gr = gi[s*GG + u], gz = gi[s*GG + 64 + u], gn = gi[s*GG + 128 + u];
            float r = 0.5f * tanh_fast(0.5f * (gr + sr + br)) + 0.5f;  // sigmoid
            float z = 0.5f * tanh_fast(0.5f * (gz + sz + bz)) + 0.5f;  // sigmoid
            float n = tanh_fast(gn + r*(sn + bn));
            float hnew = fmaf(z, h_old - n, n);      // (1-z)n + z*h
            if (half == 0) {
                h_s[u] = hnew;
                out_b[(c*CH + s)*NHH + u] = hnew;
            }
            h_old = hnew;
            __syncthreads();
        }
        // staged GI prefetch for chunk c+2 into the buffer just consumed
        if (c + 2 < NCHUNK) {
            #pragma unroll
            for (int i = 0; i < 6; i++) {
                int unit = tid + i*128;
                asm volatile("cp.async.ca.shared.global [%0], [%1], 16;"
                    :: "r"(gibase + (c & 1)*(CH*GG*4) + unit*16),
                       "l"(gi_src + (c+2)*CH*GG + unit*4));
            }
            asm volatile("cp.async.commit_group;");
            asm volatile("cp.async.wait_group 1;");   // chunk c+1 complete
        } else {
            asm volatile("cp.async.wait_group 0;");
        }
        __syncthreads();
    }
}

// -------- launch --------
extern "C" void kernel_launch(void* const* d_in, const int* in_sizes, int n_in,
                              void* d_out, int out_size) {
    const float* ts   = (const float*)d_in[0];
    const float* val  = (const float*)d_in[1];
    const int*   mark = (const int*)  d_in[2];
    const float* npm  = (const float*)d_in[3];
    const float* Wl   = (const float*)d_in[4];
    const float* bl   = (const float*)d_in[5];
    const float* Wp   = (const float*)d_in[6];
    const float* bp   = (const float*)d_in[7];
    const float* Wq   = (const float*)d_in[8];
    const float* bq   = (const float*)d_in[9];
    const float* Wk   = (const float*)d_in[10];
    const float* bk   = (const float*)d_in[11];
    const float* Wo   = (const float*)d_in[12];
    const float* bo   = (const float*)d_in[13];
    const float* W_ih = (const float*)d_in[14];
    const float* W_hh = (const float*)d_in[15];
    const float* b_ih = (const float*)d_in[16];
    const float* b_hh = (const float*)d_in[17];
    float* out = (float*)d_out;

    static int att_attr_set = 0;
    if (!att_attr_set) {
        cudaFuncSetAttribute(k_att2, cudaFuncAttributeMaxDynamicSharedMemorySize,
                             SMEM_ATT_BYTES);
        att_attr_set = 1;
    }

    k_setup<<<41, 512>>>(ts, Wl, bl, Wp, bp, Wq, bq, Wk, bk,
                         W_ih, Wo, b_ih, bo, mark, npm);
    k_att2 <<<dim3(16,8), 512, SMEM_ATT_BYTES>>>(val);
    k_gru2 <<<8, 128>>>(W_hh, b_hh, out);
}